// round 13
// baseline (speedup 1.0000x reference)
#include <cuda_runtime.h>
#include <cuda_fp16.h>
#include <math.h>
#include <stdint.h>

#define B_  64
#define T_  512
#define F_  3072
#define I_  1024
#define G4  4096
#define NC  22
#define M_  (B_*T_)     /* 32768 */
#define MP  4160        /* recurrent W'' rows: 4096 gates + 22 cls + pad */
#define NBLK 130        /* persistent grid */
#define CHUNK_BLKS 2048 /* phase-2 blocks per t-chunk (64 y-tiles x 32 x-tiles) */

// ---------------------------------------------------------------------------
// Scratch (__device__ globals; referenced ONLY from device code — R5 lesson)
// ---------------------------------------------------------------------------
__device__ __half g_f[(size_t)M_ * F_];      // features fp16, k-permuted
__device__ __half g_x[(size_t)M_ * I_];      // relu(pre) out fp16, k-permuted
__device__ float  g_gx[(size_t)T_ * B_ * G4];// gate-input precompute [t][b][4096]
__device__ __half g_Wp[(size_t)I_ * F_];
__device__ __half g_Wi[(size_t)G4 * I_];
__device__ __half g_Wr[(size_t)MP * I_];     // re-tiled [Whh;Wcls;0], k-permuted
__device__ __half g_h[2][B_ * I_];           // h fp16, double buffered, permuted
__device__ volatile unsigned g_bar;          // grid barrier counter
__device__ volatile unsigned g_done[4];      // phase-2 chunk completion counters

// k-permutation within a 32-group: lane quad c's 8 needed fp16 are contiguous.
__device__ __forceinline__ int perm32(int p) {
    return (((p & 7) >> 1) << 3) + ((p >> 3) << 1) + (p & 1);
}
__device__ __forceinline__ int permPair(int p) {   // p even
    return (((p & 7) >> 1) << 3) + ((p >> 3) << 1);
}
__device__ __forceinline__ uint32_t cvta_smem(const void* p) {
    uint32_t a;
    asm("{ .reg .u64 t; cvta.to.shared.u64 t, %1; cvt.u32.u64 %0, t; }"
        : "=r"(a) : "l"(p));
    return a;
}
// L2-coherent (L1-bypassing) accessors for cross-SM traffic
__device__ __forceinline__ uint4 ld_cg_u4(const void* p) {
    uint4 v;
    asm volatile("ld.global.cg.v4.u32 {%0,%1,%2,%3}, [%4];"
                 : "=r"(v.x), "=r"(v.y), "=r"(v.z), "=r"(v.w) : "l"(p));
    return v;
}
__device__ __forceinline__ float2 ld_cg_f2(const float* p) {
    float2 v;
    asm volatile("ld.global.cg.v2.f32 {%0,%1}, [%2];"
                 : "=f"(v.x), "=f"(v.y) : "l"(p));
    return v;
}
__device__ __forceinline__ void st_cg_u32(void* p, uint32_t v) {
    asm volatile("st.global.cg.u32 [%0], %1;" :: "l"(p), "r"(v) : "memory");
}

// ---------------------------------------------------------------------------
// Prep kernels (byte-identical to R11/R12-passing)
// ---------------------------------------------------------------------------
template<int SEL>
__global__ void prep_split(const float* __restrict__ src, int K)
{
    __half* __restrict__ dst = (SEL == 0) ? g_f : (SEL == 1) ? g_Wp : g_Wi;
    int row = blockIdx.y;
    int k = (blockIdx.x * 256 + threadIdx.x) * 2;
    float2 v = *reinterpret_cast<const float2*>(src + (size_t)row * K + k);
    int idx = (k & ~31) + permPair(k & 31);
    *reinterpret_cast<__half2*>(dst + (size_t)row * K + idx) =
        __floats2half2_rn(v.x, v.y);
}

__global__ void prep_rec(const float* __restrict__ W_hh,
                         const float* __restrict__ W_cls)
{
    int m = blockIdx.y;
    int k = (blockIdx.x * 256 + threadIdx.x) * 2;
    float2 v = make_float2(0.f, 0.f);
    if (m < 4096) {
        int s = m >> 6, loc = m & 63, g = loc >> 4, u = loc & 15;
        v = *reinterpret_cast<const float2*>(
            W_hh + (size_t)(g * 1024 + s * 16 + u) * I_ + k);
    } else if (m < 4096 + NC) {
        v = *reinterpret_cast<const float2*>(W_cls + (size_t)(m - 4096) * I_ + k);
    }
    int idx = (k & ~31) + permPair(k & 31);
    *reinterpret_cast<__half2*>(g_Wr + (size_t)m * I_ + idx) =
        __floats2half2_rn(v.x, v.y);
}

__global__ void init_state() {
    int i = blockIdx.x * blockDim.x + threadIdx.x;
    if (i < B_ * I_) g_h[0][i] = __float2half(0.f);
    if (i == 0) g_bar = 0u;
    if (i < 4) g_done[i] = 0u;
}

// ---------------------------------------------------------------------------
// fp16 m16n8k16 MMA, fp32 accumulate
// ---------------------------------------------------------------------------
#define MMAF16(d, a0, a1, a2, a3, b0, b1)                                     \
    asm volatile("mma.sync.aligned.m16n8k16.row.col.f32.f16.f16.f32 "        \
                 "{%0,%1,%2,%3}, {%4,%5,%6,%7}, {%8,%9}, {%0,%1,%2,%3};"     \
                 : "+f"(d[0]), "+f"(d[1]), "+f"(d[2]), "+f"(d[3])            \
                 : "r"(a0), "r"(a1), "r"(a2), "r"(a3), "r"(b0), "r"(b1))

#define MMA_K32(acc, A0, A1, Bv)                                              \
    do {                                                                      \
        MMAF16(acc, A0.x, A1.x, A0.y, A1.y, Bv.x, Bv.y);                      \
        MMAF16(acc, A0.z, A1.z, A0.w, A1.w, Bv.z, Bv.w);                      \
    } while (0)

// ---------------------------------------------------------------------------
// SMEM-staged phase GEMMs (R11 structure; MODE 1 adds chunk-done signalling)
// ---------------------------------------------------------------------------
template<int K, int MODE>
__global__ __launch_bounds__(256, 1) void mma_gemm_s(const float* __restrict__ bias0,
                                                     const float* __restrict__ bias1)
{
    extern __shared__ char sm[];
    const __half* __restrict__ gA = MODE ? g_x : g_f;
    const __half* __restrict__ gB = MODE ? g_Wi : g_Wp;

    const int tid = threadIdx.x, w = tid >> 5, lane = tid & 31;
    const int mw = w & 1, nw = w >> 1;
    const int r = lane >> 2, c = lane & 3;
    const int m0 = blockIdx.y * 128, n0 = blockIdx.x * 128;
    const uint32_t sbase = cvta_smem(sm);

    auto stage = [&](int q, int buf) {
        const size_t gk = (size_t)q * 32;
#pragma unroll
        for (int t = 0; t < 4; t++) {
            int i = tid + t * 256;
            int plane = i >> 9, o = i & 511, row = o >> 2, seg = o & 3;
            const __half* gp = plane ? gB : gA;
            int grow = (plane ? n0 : m0) + row;
            const __half* src = gp + (size_t)grow * K + gk + seg * 8;
            uint32_t dst = sbase + (uint32_t)(buf * 16384 + plane * 8192 +
                                              row * 64 + seg * 16);
            asm volatile("cp.async.cg.shared.global [%0], [%1], 16;"
                         :: "r"(dst), "l"(__cvta_generic_to_global(src)));
        }
        asm volatile("cp.async.commit_group;" ::: "memory");
    };

    float acc[4][4][4];
#pragma unroll
    for (int i = 0; i < 4; i++)
#pragma unroll
        for (int j = 0; j < 4; j++)
#pragma unroll
            for (int q = 0; q < 4; q++) acc[i][j][q] = 0.f;

    const int NK = K / 32;
    stage(0, 0);

    for (int q = 0; q < NK; q++) {
        asm volatile("cp.async.wait_group 0;" ::: "memory");
        __syncthreads();
        if (q + 1 < NK) stage(q + 1, (q + 1) & 1);

        const char* bufp = sm + (q & 1) * 16384;
        const uint4* A = reinterpret_cast<const uint4*>(bufp);
        const uint4* Bv = reinterpret_cast<const uint4*>(bufp + 8192);

        uint4 bf[4];
#pragma unroll
        for (int j = 0; j < 4; j++) {
            int row = nw * 32 + j * 8 + r;
            bf[j] = Bv[row * 4 + c];
        }
#pragma unroll
        for (int i = 0; i < 4; i++) {
            int row0 = mw * 64 + i * 16 + r;
            uint4 a0 = A[row0 * 4 + c];
            uint4 a1 = A[(row0 + 8) * 4 + c];
#pragma unroll
            for (int j = 0; j < 4; j++)
                MMA_K32(acc[i][j], a0, a1, bf[j]);
        }
        __syncthreads();
    }

#pragma unroll
    for (int i = 0; i < 4; i++) {
#pragma unroll
        for (int h = 0; h < 2; h++) {
            int m = m0 + mw * 64 + i * 16 + r + h * 8;
            if (MODE == 0) {
                int ngrp = n0 + nw * 32;
                uint32_t hp[4];
#pragma unroll
                for (int j = 0; j < 4; j++) {
                    int n = ngrp + j * 8 + 2 * c;
                    float v0 = fmaxf(acc[i][j][2 * h]     + bias0[n],     0.f);
                    float v1 = fmaxf(acc[i][j][2 * h + 1] + bias0[n + 1], 0.f);
                    __half2 hh = __floats2half2_rn(v0, v1);
                    hp[j] = *reinterpret_cast<uint32_t*>(&hh);
                }
                int nidx0 = ngrp + 8 * c;
                *reinterpret_cast<uint4*>(g_x + (size_t)m * I_ + nidx0) =
                    make_uint4(hp[0], hp[1], hp[2], hp[3]);
            } else {
                int bb = m >> 9, tt = m & 511;
                float* op = g_gx + ((size_t)tt * B_ + bb) * G4;
#pragma unroll
                for (int j = 0; j < 4; j++) {
                    int n = n0 + nw * 32 + j * 8 + 2 * c;
                    float2 o;
                    o.x = acc[i][j][2 * h]     + bias0[n]     + bias1[n];
                    o.y = acc[i][j][2 * h + 1] + bias0[n + 1] + bias1[n + 1];
                    *reinterpret_cast<float2*>(op + n) = o;
                }
            }
        }
    }

    if (MODE == 1) {
        // signal t-chunk completion (y-tile covers t in [ (y&3)*128, +128 ))
        __syncthreads();
        if (tid == 0) {
            __threadfence();
            atomicAdd((unsigned*)&g_done[blockIdx.y & 3], 1u);
        }
    }
}

// ---------------------------------------------------------------------------
// Persistent recurrence. Per step: barrier -> chunk-ready poll -> gx prefetch
// -> MMA (4 independent chains/warp via k-half split) -> cell -> half2 h store.
// ---------------------------------------------------------------------------
__device__ __forceinline__ float sigf(float x) { return 1.f / (1.f + expf(-x)); }

__device__ __forceinline__ void grid_bar(unsigned target) {
    __syncthreads();
    if (threadIdx.x == 0) {
        __threadfence();                       // release prior .cg stores
        atomicAdd((unsigned*)&g_bar, 1u);
        unsigned ns = 8;
        while (g_bar < target) {
            __nanosleep(ns);
            if (ns < 256) ns <<= 1;
        }
        __threadfence();                       // acquire
    }
    __syncthreads();
}

__global__ __launch_bounds__(256, 1) void lstm_persist(float* __restrict__ out,
                                                       const float* __restrict__ b_cls)
{
    const int blk = blockIdx.x;
    const bool is_cls = blk >= 128;
    const int s  = is_cls ? 64 : (blk >> 1);
    const int nb = is_cls ? (blk - 128) : (blk & 1);
    const int tid = threadIdx.x, w = tid >> 5, lane = tid & 31;
    const int mw = w & 3, nw = w >> 2;
    const int r = lane >> 2, c = lane & 3;
    const int m0 = s * 64 + mw * 16;
    const int bb0 = nb * 32 + nw * 16;

    __shared__ float Ds[64][33];
    __shared__ float cs[32][16];
    if (!is_cls)
        for (int e = tid; e < 512; e += 256) cs[e >> 4][e & 15] = 0.f;

    // this thread's epilogue coordinates (pair-based)
    const int eb = tid >> 3, epr = tid & 7;        // batch-in-half, k-pair
    const int ebatch = nb * 32 + eb;
    const int ek = s * 16 + 2 * epr;
    const int ehidx = (ek & ~31) + permPair(ek & 31);

    const __half* pA = g_Wr + (size_t)(m0 + r) * I_ + c * 8;
    const size_t A8 = (size_t)8 * I_;

    for (int t = 0; t <= T_; t++) {
        grid_bar((unsigned)(t + 1) * NBLK);
        const bool active = is_cls ? (t >= 1) : (t < T_);
        if (!active) continue;
        const int p = t & 1;

        // gx chunk-ready poll + prefetch (gate blocks only)
        float2 gxv[4];
        if (!is_cls) {
            if (tid == 0) {
                unsigned ns = 8;
                while (g_done[t >> 7] < CHUNK_BLKS) {
                    __nanosleep(ns);
                    if (ns < 256) ns <<= 1;
                }
                __threadfence();               // acquire gx data
            }
            __syncthreads();
            const float* gxp = g_gx + ((size_t)t * B_ + ebatch) * G4 + s * 16 + 2 * epr;
#pragma unroll
            for (int g = 0; g < 4; g++)
                gxv[g] = ld_cg_f2(gxp + g * 1024);
        }

        const __half* pB = g_h[p] + (size_t)(bb0 + r) * I_ + c * 8;

        float accA[2][4], accB[2][4];
#pragma unroll
        for (int j = 0; j < 2; j++)
#pragma unroll
            for (int q = 0; q < 4; q++) { accA[j][q] = 0.f; accB[j][q] = 0.f; }

#pragma unroll 4
        for (int q = 0; q < 16; q++) {
            int offA = q * 32, offB = (q + 16) * 32;
            uint4 a0A = *reinterpret_cast<const uint4*>(pA + offA);
            uint4 a1A = *reinterpret_cast<const uint4*>(pA + A8 + offA);
            uint4 a0B = *reinterpret_cast<const uint4*>(pA + offB);
            uint4 a1B = *reinterpret_cast<const uint4*>(pA + A8 + offB);
#pragma unroll
            for (int j = 0; j < 2; j++) {
                uint4 bvA = ld_cg_u4(pB + (size_t)j * A8 + offA);
                uint4 bvB = ld_cg_u4(pB + (size_t)j * A8 + offB);
                MMA_K32(accA[j], a0A, a1A, bvA);
                MMA_K32(accB[j], a0B, a1B, bvB);
            }
        }
        float acc[2][4];
#pragma unroll
        for (int j = 0; j < 2; j++)
#pragma unroll
            for (int q = 0; q < 4; q++) acc[j][q] = accA[j][q] + accB[j][q];

        if (is_cls) {
            int tq = t - 1;
#pragma unroll
            for (int j = 0; j < 2; j++) {
                int bA = bb0 + j * 8 + 2 * c;
                int row0 = mw * 16 + r, row1 = row0 + 8;
                if (row0 < NC) {
                    float bc = b_cls[row0];
                    out[((size_t)bA       * T_ + tq) * NC + row0] = acc[j][0] + bc;
                    out[((size_t)(bA + 1) * T_ + tq) * NC + row0] = acc[j][1] + bc;
                }
                if (row1 < NC) {
                    float bc = b_cls[row1];
                    out[((size_t)bA       * T_ + tq) * NC + row1] = acc[j][2] + bc;
                    out[((size_t)(bA + 1) * T_ + tq) * NC + row1] = acc[j][3] + bc;
                }
            }
            continue;
        }

#pragma unroll
        for (int j = 0; j < 2; j++) {
            int col = nw * 16 + j * 8 + 2 * c;
            Ds[mw * 16 + r    ][col    ] = acc[j][0];
            Ds[mw * 16 + r    ][col + 1] = acc[j][1];
            Ds[mw * 16 + r + 8][col    ] = acc[j][2];
            Ds[mw * 16 + r + 8][col + 1] = acc[j][3];
        }
        __syncthreads();

        // fused cell update, one k-pair per thread; half2 h store
        {
            int u0 = 2 * epr, u1 = u0 + 1;
            float gi0 = Ds[u0][eb]      + gxv[0].x;
            float gi1 = Ds[u1][eb]      + gxv[0].y;
            float gf0 = Ds[16 + u0][eb] + gxv[1].x;
            float gf1 = Ds[16 + u1][eb] + gxv[1].y;
            float gg0 = Ds[32 + u0][eb] + gxv[2].x;
            float gg1 = Ds[32 + u1][eb] + gxv[2].y;
            float go0 = Ds[48 + u0][eb] + gxv[3].x;
            float go1 = Ds[48 + u1][eb] + gxv[3].y;
            float cn0 = sigf(gf0) * cs[eb][u0] + sigf(gi0) * tanhf(gg0);
            float cn1 = sigf(gf1) * cs[eb][u1] + sigf(gi1) * tanhf(gg1);
            cs[eb][u0] = cn0;
            cs[eb][u1] = cn1;
            __half2 hv = __floats2half2_rn(sigf(go0) * tanhf(cn0),
                                           sigf(go1) * tanhf(cn1));
            st_cg_u32(&g_h[(t + 1) & 1][(size_t)ebatch * I_ + ehidx],
                      *reinterpret_cast<uint32_t*>(&hv));
        }
        __syncthreads();   // cs/Ds reuse safety before next iteration
    }
}

// ---------------------------------------------------------------------------
extern "C" void kernel_launch(void* const* d_in, const int* in_sizes, int n_in,
                              void* d_out, int out_size)
{
    (void)in_sizes; (void)n_in; (void)out_size;
    const float* feat  = (const float*)d_in[0];
    const float* W_pre = (const float*)d_in[1];
    const float* b_pre = (const float*)d_in[2];
    const float* W_ih  = (const float*)d_in[3];
    const float* b_ih  = (const float*)d_in[4];
    const float* W_hh  = (const float*)d_in[5];
    const float* b_hh  = (const float*)d_in[6];
    const float* W_cls = (const float*)d_in[7];
    const float* b_cls = (const float*)d_in[8];
    float* out = (float*)d_out;

    const int SMEM_DYN = 2 * 16384;

    // One-time fork/join stream + events (no device memory involved)
    static cudaStream_t s2 = nullptr;
    static cudaEvent_t ev_fork, ev_join;
    if (!s2) {
        cudaStreamCreateWithFlags(&s2, cudaStreamNonBlocking);
        cudaEventCreateWithFlags(&ev_fork, cudaEventDisableTiming);
        cudaEventCreateWithFlags(&ev_join, cudaEventDisableTiming);
    }

    prep_split<0><<<dim3(F_ / 512, M_), 256>>>(feat,  F_);
    prep_split<1><<<dim3(F_ / 512, I_), 256>>>(W_pre, F_);
    prep_split<2><<<dim3(I_ / 512, G4), 256>>>(W_ih,  I_);

    // Phase 1: x = relu(feat @ W_pre^T + b_pre)      M=32768 N=1024 K=3072
    mma_gemm_s<F_, 0><<<dim3(1024 / 128, M_ / 128), 256, SMEM_DYN>>>(b_pre, nullptr);

    prep_rec<<<dim3(I_ / 512, MP), 256>>>(W_hh, W_cls);
    init_state<<<(B_ * I_ + 255) / 256, 256>>>();

    // Fork: persistent recurrence starts now (polls g_done for gx chunks).
    cudaEventRecord(ev_fork, 0);
    cudaStreamWaitEvent(s2, ev_fork, 0);
    lstm_persist<<<NBLK, 256, 0, s2>>>(out, b_cls);

    // Phase 2 (concurrent producer): gx = x @ W_ih^T + b_ih + b_hh
    mma_gemm_s<I_, 1><<<dim3(G4 / 128, M_ / 128), 256, SMEM_DYN>>>(b_ih, b_hh);

    // Join
    cudaEventRecord(ev_join, s2);
    cudaStreamWaitEvent(0, ev_join, 0);
}

// round 14
// speedup vs baseline: 1.9124x; 1.9124x over previous
#include <cuda_runtime.h>
#include <cuda_fp16.h>
#include <math.h>
#include <stdint.h>

#define B_  64
#define T_  512
#define F_  3072
#define I_  1024
#define G4  4096
#define NC  22
#define M_  (B_*T_)     /* 32768 */
#define MP  4160        /* recurrent W'' rows: 4096 gates + 22 cls + pad */
#define NBLK 130        /* persistent grid */

// ---------------------------------------------------------------------------
// Scratch (__device__ globals; referenced ONLY from device code — R5 lesson)
// ---------------------------------------------------------------------------
__device__ __half g_f[(size_t)M_ * F_];      // features fp16, k-permuted
__device__ __half g_x[(size_t)M_ * I_];      // relu(pre) out fp16, k-permuted
__device__ float  g_gx[(size_t)T_ * B_ * G4];// gate-input precompute [t][b][4096]
__device__ __half g_Wp[(size_t)I_ * F_];
__device__ __half g_Wi[(size_t)G4 * I_];
__device__ __half g_Wr[(size_t)MP * I_];     // re-tiled [Whh;Wcls;0], k-permuted
__device__ __half g_h[2][B_ * I_];           // h fp16, double buffered, permuted
__device__ volatile unsigned g_bar;          // grid barrier counter

// k-permutation within a 32-group: lane quad c's 8 needed fp16 are contiguous.
__device__ __forceinline__ int perm32(int p) {
    return (((p & 7) >> 1) << 3) + ((p >> 3) << 1) + (p & 1);
}
__device__ __forceinline__ int permPair(int p) {   // p even
    return (((p & 7) >> 1) << 3) + ((p >> 3) << 1);
}
__device__ __forceinline__ uint32_t cvta_smem(const void* p) {
    uint32_t a;
    asm("{ .reg .u64 t; cvta.to.shared.u64 t, %1; cvt.u32.u64 %0, t; }"
        : "=r"(a) : "l"(p));
    return a;
}
// L2-coherent (L1-bypassing) accessors for cross-SM traffic
__device__ __forceinline__ uint4 ld_cg_u4(const void* p) {
    uint4 v;
    asm volatile("ld.global.cg.v4.u32 {%0,%1,%2,%3}, [%4];"
                 : "=r"(v.x), "=r"(v.y), "=r"(v.z), "=r"(v.w) : "l"(p));
    return v;
}
__device__ __forceinline__ float2 ld_cg_f2(const float* p) {
    float2 v;
    asm volatile("ld.global.cg.v2.f32 {%0,%1}, [%2];"
                 : "=f"(v.x), "=f"(v.y) : "l"(p));
    return v;
}
__device__ __forceinline__ void st_cg_u32(void* p, uint32_t v) {
    asm volatile("st.global.cg.u32 [%0], %1;" :: "l"(p), "r"(v) : "memory");
}

// ---------------------------------------------------------------------------
// Prep kernels (byte-identical to R11/R12-passing)
// ---------------------------------------------------------------------------
template<int SEL>
__global__ void prep_split(const float* __restrict__ src, int K)
{
    __half* __restrict__ dst = (SEL == 0) ? g_f : (SEL == 1) ? g_Wp : g_Wi;
    int row = blockIdx.y;
    int k = (blockIdx.x * 256 + threadIdx.x) * 2;
    float2 v = *reinterpret_cast<const float2*>(src + (size_t)row * K + k);
    int idx = (k & ~31) + permPair(k & 31);
    *reinterpret_cast<__half2*>(dst + (size_t)row * K + idx) =
        __floats2half2_rn(v.x, v.y);
}

__global__ void prep_rec(const float* __restrict__ W_hh,
                         const float* __restrict__ W_cls)
{
    int m = blockIdx.y;
    int k = (blockIdx.x * 256 + threadIdx.x) * 2;
    float2 v = make_float2(0.f, 0.f);
    if (m < 4096) {
        int s = m >> 6, loc = m & 63, g = loc >> 4, u = loc & 15;
        v = *reinterpret_cast<const float2*>(
            W_hh + (size_t)(g * 1024 + s * 16 + u) * I_ + k);
    } else if (m < 4096 + NC) {
        v = *reinterpret_cast<const float2*>(W_cls + (size_t)(m - 4096) * I_ + k);
    }
    int idx = (k & ~31) + permPair(k & 31);
    *reinterpret_cast<__half2*>(g_Wr + (size_t)m * I_ + idx) =
        __floats2half2_rn(v.x, v.y);
}

__global__ void init_state() {
    int i = blockIdx.x * blockDim.x + threadIdx.x;
    if (i < B_ * I_) g_h[0][i] = __float2half(0.f);
    if (i == 0) g_bar = 0u;
}

// ---------------------------------------------------------------------------
// fp16 m16n8k16 MMA, fp32 accumulate
// ---------------------------------------------------------------------------
#define MMAF16(d, a0, a1, a2, a3, b0, b1)                                     \
    asm volatile("mma.sync.aligned.m16n8k16.row.col.f32.f16.f16.f32 "        \
                 "{%0,%1,%2,%3}, {%4,%5,%6,%7}, {%8,%9}, {%0,%1,%2,%3};"     \
                 : "+f"(d[0]), "+f"(d[1]), "+f"(d[2]), "+f"(d[3])            \
                 : "r"(a0), "r"(a1), "r"(a2), "r"(a3), "r"(b0), "r"(b1))

#define MMA_K32(acc, A0, A1, Bv)                                              \
    do {                                                                      \
        MMAF16(acc, A0.x, A1.x, A0.y, A1.y, Bv.x, Bv.y);                      \
        MMAF16(acc, A0.z, A1.z, A0.w, A1.w, Bv.z, Bv.w);                      \
    } while (0)

// ---------------------------------------------------------------------------
// SMEM-staged phase GEMMs (byte-identical to R11/R12-passing)
// ---------------------------------------------------------------------------
template<int K, int MODE>
__global__ __launch_bounds__(256, 1) void mma_gemm_s(const float* __restrict__ bias0,
                                                     const float* __restrict__ bias1)
{
    extern __shared__ char sm[];
    const __half* __restrict__ gA = MODE ? g_x : g_f;
    const __half* __restrict__ gB = MODE ? g_Wi : g_Wp;

    const int tid = threadIdx.x, w = tid >> 5, lane = tid & 31;
    const int mw = w & 1, nw = w >> 1;
    const int r = lane >> 2, c = lane & 3;
    const int m0 = blockIdx.y * 128, n0 = blockIdx.x * 128;
    const uint32_t sbase = cvta_smem(sm);

    auto stage = [&](int q, int buf) {
        const size_t gk = (size_t)q * 32;
#pragma unroll
        for (int t = 0; t < 4; t++) {
            int i = tid + t * 256;
            int plane = i >> 9, o = i & 511, row = o >> 2, seg = o & 3;
            const __half* gp = plane ? gB : gA;
            int grow = (plane ? n0 : m0) + row;
            const __half* src = gp + (size_t)grow * K + gk + seg * 8;
            uint32_t dst = sbase + (uint32_t)(buf * 16384 + plane * 8192 +
                                              row * 64 + seg * 16);
            asm volatile("cp.async.cg.shared.global [%0], [%1], 16;"
                         :: "r"(dst), "l"(__cvta_generic_to_global(src)));
        }
        asm volatile("cp.async.commit_group;" ::: "memory");
    };

    float acc[4][4][4];
#pragma unroll
    for (int i = 0; i < 4; i++)
#pragma unroll
        for (int j = 0; j < 4; j++)
#pragma unroll
            for (int q = 0; q < 4; q++) acc[i][j][q] = 0.f;

    const int NK = K / 32;
    stage(0, 0);

    for (int q = 0; q < NK; q++) {
        asm volatile("cp.async.wait_group 0;" ::: "memory");
        __syncthreads();
        if (q + 1 < NK) stage(q + 1, (q + 1) & 1);

        const char* bufp = sm + (q & 1) * 16384;
        const uint4* A = reinterpret_cast<const uint4*>(bufp);
        const uint4* Bv = reinterpret_cast<const uint4*>(bufp + 8192);

        uint4 bf[4];
#pragma unroll
        for (int j = 0; j < 4; j++) {
            int row = nw * 32 + j * 8 + r;
            bf[j] = Bv[row * 4 + c];
        }
#pragma unroll
        for (int i = 0; i < 4; i++) {
            int row0 = mw * 64 + i * 16 + r;
            uint4 a0 = A[row0 * 4 + c];
            uint4 a1 = A[(row0 + 8) * 4 + c];
#pragma unroll
            for (int j = 0; j < 4; j++)
                MMA_K32(acc[i][j], a0, a1, bf[j]);
        }
        __syncthreads();
    }

#pragma unroll
    for (int i = 0; i < 4; i++) {
#pragma unroll
        for (int h = 0; h < 2; h++) {
            int m = m0 + mw * 64 + i * 16 + r + h * 8;
            if (MODE == 0) {
                int ngrp = n0 + nw * 32;
                uint32_t hp[4];
#pragma unroll
                for (int j = 0; j < 4; j++) {
                    int n = ngrp + j * 8 + 2 * c;
                    float v0 = fmaxf(acc[i][j][2 * h]     + bias0[n],     0.f);
                    float v1 = fmaxf(acc[i][j][2 * h + 1] + bias0[n + 1], 0.f);
                    __half2 hh = __floats2half2_rn(v0, v1);
                    hp[j] = *reinterpret_cast<uint32_t*>(&hh);
                }
                int nidx0 = ngrp + 8 * c;
                *reinterpret_cast<uint4*>(g_x + (size_t)m * I_ + nidx0) =
                    make_uint4(hp[0], hp[1], hp[2], hp[3]);
            } else {
                int bb = m >> 9, tt = m & 511;
                float* op = g_gx + ((size_t)tt * B_ + bb) * G4;
#pragma unroll
                for (int j = 0; j < 4; j++) {
                    int n = n0 + nw * 32 + j * 8 + 2 * c;
                    float2 o;
                    o.x = acc[i][j][2 * h]     + bias0[n]     + bias1[n];
                    o.y = acc[i][j][2 * h + 1] + bias0[n + 1] + bias1[n + 1];
                    *reinterpret_cast<float2*>(op + n) = o;
                }
            }
        }
    }
}

// ---------------------------------------------------------------------------
// Persistent recurrence (serial after phase-2). Per step: barrier ->
// gx register prefetch -> MMA (4 independent chains/warp) -> cell -> half2 st.
// ---------------------------------------------------------------------------
__device__ __forceinline__ float sigf(float x) { return 1.f / (1.f + expf(-x)); }

__device__ __forceinline__ void grid_bar(unsigned target) {
    __syncthreads();
    if (threadIdx.x == 0) {
        __threadfence();                       // release prior .cg stores
        atomicAdd((unsigned*)&g_bar, 1u);
        unsigned ns = 8;
        while (g_bar < target) {
            __nanosleep(ns);
            if (ns < 256) ns <<= 1;
        }
        __threadfence();                       // acquire
    }
    __syncthreads();
}

__global__ __launch_bounds__(256, 1) void lstm_persist(float* __restrict__ out,
                                                       const float* __restrict__ b_cls)
{
    const int blk = blockIdx.x;
    const bool is_cls = blk >= 128;
    const int s  = is_cls ? 64 : (blk >> 1);
    const int nb = is_cls ? (blk - 128) : (blk & 1);
    const int tid = threadIdx.x, w = tid >> 5, lane = tid & 31;
    const int mw = w & 3, nw = w >> 2;
    const int r = lane >> 2, c = lane & 3;
    const int m0 = s * 64 + mw * 16;
    const int bb0 = nb * 32 + nw * 16;

    __shared__ float Ds[64][33];
    __shared__ float cs[32][16];
    if (!is_cls)
        for (int e = tid; e < 512; e += 256) cs[e >> 4][e & 15] = 0.f;

    // epilogue coordinates (pair-based)
    const int eb = tid >> 3, epr = tid & 7;        // batch-in-half, k-pair
    const int ebatch = nb * 32 + eb;
    const int ek = s * 16 + 2 * epr;
    const int ehidx = (ek & ~31) + permPair(ek & 31);

    const __half* pA = g_Wr + (size_t)(m0 + r) * I_ + c * 8;
    const size_t A8 = (size_t)8 * I_;

    for (int t = 0; t <= T_; t++) {
        grid_bar((unsigned)(t + 1) * NBLK);
        const bool active = is_cls ? (t >= 1) : (t < T_);
        if (!active) continue;
        const int p = t & 1;

        // gx register prefetch (gate blocks only) — hides DRAM latency under MMA
        float2 gxv[4];
        if (!is_cls) {
            const float* gxp = g_gx + ((size_t)t * B_ + ebatch) * G4 + s * 16 + 2 * epr;
#pragma unroll
            for (int g = 0; g < 4; g++)
                gxv[g] = ld_cg_f2(gxp + g * 1024);
        }

        const __half* pB = g_h[p] + (size_t)(bb0 + r) * I_ + c * 8;

        float accA[2][4], accB[2][4];
#pragma unroll
        for (int j = 0; j < 2; j++)
#pragma unroll
            for (int q = 0; q < 4; q++) { accA[j][q] = 0.f; accB[j][q] = 0.f; }

#pragma unroll 4
        for (int q = 0; q < 16; q++) {
            int offA = q * 32, offB = (q + 16) * 32;
            uint4 a0A = *reinterpret_cast<const uint4*>(pA + offA);
            uint4 a1A = *reinterpret_cast<const uint4*>(pA + A8 + offA);
            uint4 a0B = *reinterpret_cast<const uint4*>(pA + offB);
            uint4 a1B = *reinterpret_cast<const uint4*>(pA + A8 + offB);
#pragma unroll
            for (int j = 0; j < 2; j++) {
                uint4 bvA = ld_cg_u4(pB + (size_t)j * A8 + offA);
                uint4 bvB = ld_cg_u4(pB + (size_t)j * A8 + offB);
                MMA_K32(accA[j], a0A, a1A, bvA);
                MMA_K32(accB[j], a0B, a1B, bvB);
            }
        }
        float acc[2][4];
#pragma unroll
        for (int j = 0; j < 2; j++)
#pragma unroll
            for (int q = 0; q < 4; q++) acc[j][q] = accA[j][q] + accB[j][q];

        if (is_cls) {
            int tq = t - 1;
#pragma unroll
            for (int j = 0; j < 2; j++) {
                int bA = bb0 + j * 8 + 2 * c;
                int row0 = mw * 16 + r, row1 = row0 + 8;
                if (row0 < NC) {
                    float bc = b_cls[row0];
                    out[((size_t)bA       * T_ + tq) * NC + row0] = acc[j][0] + bc;
                    out[((size_t)(bA + 1) * T_ + tq) * NC + row0] = acc[j][1] + bc;
                }
                if (row1 < NC) {
                    float bc = b_cls[row1];
                    out[((size_t)bA       * T_ + tq) * NC + row1] = acc[j][2] + bc;
                    out[((size_t)(bA + 1) * T_ + tq) * NC + row1] = acc[j][3] + bc;
                }
            }
            continue;
        }

#pragma unroll
        for (int j = 0; j < 2; j++) {
            int col = nw * 16 + j * 8 + 2 * c;
            Ds[mw * 16 + r    ][col    ] = acc[j][0];
            Ds[mw * 16 + r    ][col + 1] = acc[j][1];
            Ds[mw * 16 + r + 8][col    ] = acc[j][2];
            Ds[mw * 16 + r + 8][col + 1] = acc[j][3];
        }
        __syncthreads();

        // fused cell update, one k-pair per thread; half2 h store
        {
            int u0 = 2 * epr, u1 = u0 + 1;
            float gi0 = Ds[u0][eb]      + gxv[0].x;
            float gi1 = Ds[u1][eb]      + gxv[0].y;
            float gf0 = Ds[16 + u0][eb] + gxv[1].x;
            float gf1 = Ds[16 + u1][eb] + gxv[1].y;
            float gg0 = Ds[32 + u0][eb] + gxv[2].x;
            float gg1 = Ds[32 + u1][eb] + gxv[2].y;
            float go0 = Ds[48 + u0][eb] + gxv[3].x;
            float go1 = Ds[48 + u1][eb] + gxv[3].y;
            float cn0 = sigf(gf0) * cs[eb][u0] + sigf(gi0) * tanhf(gg0);
            float cn1 = sigf(gf1) * cs[eb][u1] + sigf(gi1) * tanhf(gg1);
            cs[eb][u0] = cn0;
            cs[eb][u1] = cn1;
            __half2 hv = __floats2half2_rn(sigf(go0) * tanhf(cn0),
                                           sigf(go1) * tanhf(cn1));
            st_cg_u32(&g_h[(t + 1) & 1][(size_t)ebatch * I_ + ehidx],
                      *reinterpret_cast<uint32_t*>(&hv));
        }
        __syncthreads();   // cs/Ds reuse safety before next iteration
    }
}

// ---------------------------------------------------------------------------
extern "C" void kernel_launch(void* const* d_in, const int* in_sizes, int n_in,
                              void* d_out, int out_size)
{
    (void)in_sizes; (void)n_in; (void)out_size;
    const float* feat  = (const float*)d_in[0];
    const float* W_pre = (const float*)d_in[1];
    const float* b_pre = (const float*)d_in[2];
    const float* W_ih  = (const float*)d_in[3];
    const float* b_ih  = (const float*)d_in[4];
    const float* W_hh  = (const float*)d_in[5];
    const float* b_hh  = (const float*)d_in[6];
    const float* W_cls = (const float*)d_in[7];
    const float* b_cls = (const float*)d_in[8];
    float* out = (float*)d_out;

    const int SMEM_DYN = 2 * 16384;

    prep_split<0><<<dim3(F_ / 512, M_), 256>>>(feat,  F_);
    prep_split<1><<<dim3(F_ / 512, I_), 256>>>(W_pre, F_);
    prep_split<2><<<dim3(I_ / 512, G4), 256>>>(W_ih,  I_);

    // Phase 1: x = relu(feat @ W_pre^T + b_pre)      M=32768 N=1024 K=3072
    mma_gemm_s<F_, 0><<<dim3(1024 / 128, M_ / 128), 256, SMEM_DYN>>>(b_pre, nullptr);

    prep_rec<<<dim3(I_ / 512, MP), 256>>>(W_hh, W_cls);
    init_state<<<(B_ * I_ + 255) / 256, 256>>>();

    // Phase 2: gx[t][b] = x @ W_ih^T + b_ih + b_hh   M=32768 N=4096 K=1024
    mma_gemm_s<I_, 1><<<dim3(G4 / 128, M_ / 128), 256, SMEM_DYN>>>(b_ih, b_hh);

    // Phase 3: full recurrence in ONE persistent kernel (serial, 513 rounds)
    lstm_persist<<<NBLK, 256>>>(out, b_cls);
}

// round 15
// speedup vs baseline: 1.9848x; 1.0378x over previous
#include <cuda_runtime.h>
#include <cuda_fp16.h>
#include <math.h>
#include <stdint.h>

#define B_  64
#define T_  512
#define F_  3072
#define I_  1024
#define G4  4096
#define NC  22
#define M_  (B_*T_)     /* 32768 */
#define MP  4160        /* recurrent W'' rows: 4096 gates + 22 cls + pad */
#define NBLK 130        /* persistent grid */
#define GRP  65         /* blocks per barrier group (one batch half) */

// ---------------------------------------------------------------------------
// Scratch (__device__ globals; referenced ONLY from device code — R5 lesson)
// ---------------------------------------------------------------------------
__device__ __half g_f[(size_t)M_ * F_];      // features fp16, k-permuted
__device__ __half g_x[(size_t)M_ * I_];      // relu(pre) out fp16, k-permuted
__device__ float  g_gx[(size_t)T_ * B_ * G4];// gate-input precompute [t][b][4096]
__device__ __half g_Wp[(size_t)I_ * F_];
__device__ __half g_Wi[(size_t)G4 * I_];
__device__ __half g_Wr[(size_t)MP * I_];     // re-tiled [Whh;Wcls;0], k-permuted
__device__ __half g_h[2][B_ * I_];           // h fp16, double buffered, permuted
__device__ unsigned g_barG[64];              // 2 group counters, 128B apart

// k-permutation within a 32-group: lane quad c's 8 needed fp16 are contiguous.
__device__ __forceinline__ int perm32(int p) {
    return (((p & 7) >> 1) << 3) + ((p >> 3) << 1) + (p & 1);
}
__device__ __forceinline__ int permPair(int p) {   // p even
    return (((p & 7) >> 1) << 3) + ((p >> 3) << 1);
}
__device__ __forceinline__ uint32_t cvta_smem(const void* p) {
    uint32_t a;
    asm("{ .reg .u64 t; cvta.to.shared.u64 t, %1; cvt.u32.u64 %0, t; }"
        : "=r"(a) : "l"(p));
    return a;
}
// L2-coherent (L1-bypassing) accessors for cross-SM traffic
__device__ __forceinline__ uint4 ld_cg_u4(const void* p) {
    uint4 v;
    asm volatile("ld.global.cg.v4.u32 {%0,%1,%2,%3}, [%4];"
                 : "=r"(v.x), "=r"(v.y), "=r"(v.z), "=r"(v.w) : "l"(p));
    return v;
}
__device__ __forceinline__ float2 ld_cg_f2(const float* p) {
    float2 v;
    asm volatile("ld.global.cg.v2.f32 {%0,%1}, [%2];"
                 : "=f"(v.x), "=f"(v.y) : "l"(p));
    return v;
}
__device__ __forceinline__ void st_cg_u32(void* p, uint32_t v) {
    asm volatile("st.global.cg.u32 [%0], %1;" :: "l"(p), "r"(v) : "memory");
}

// ---------------------------------------------------------------------------
// Prep kernels (byte-identical to R11..R14-passing)
// ---------------------------------------------------------------------------
template<int SEL>
__global__ void prep_split(const float* __restrict__ src, int K)
{
    __half* __restrict__ dst = (SEL == 0) ? g_f : (SEL == 1) ? g_Wp : g_Wi;
    int row = blockIdx.y;
    int k = (blockIdx.x * 256 + threadIdx.x) * 2;
    float2 v = *reinterpret_cast<const float2*>(src + (size_t)row * K + k);
    int idx = (k & ~31) + permPair(k & 31);
    *reinterpret_cast<__half2*>(dst + (size_t)row * K + idx) =
        __floats2half2_rn(v.x, v.y);
}

__global__ void prep_rec(const float* __restrict__ W_hh,
                         const float* __restrict__ W_cls)
{
    int m = blockIdx.y;
    int k = (blockIdx.x * 256 + threadIdx.x) * 2;
    float2 v = make_float2(0.f, 0.f);
    if (m < 4096) {
        int s = m >> 6, loc = m & 63, g = loc >> 4, u = loc & 15;
        v = *reinterpret_cast<const float2*>(
            W_hh + (size_t)(g * 1024 + s * 16 + u) * I_ + k);
    } else if (m < 4096 + NC) {
        v = *reinterpret_cast<const float2*>(W_cls + (size_t)(m - 4096) * I_ + k);
    }
    int idx = (k & ~31) + permPair(k & 31);
    *reinterpret_cast<__half2*>(g_Wr + (size_t)m * I_ + idx) =
        __floats2half2_rn(v.x, v.y);
}

__global__ void init_state() {
    int i = blockIdx.x * blockDim.x + threadIdx.x;
    if (i < B_ * I_) g_h[0][i] = __float2half(0.f);
    if (i < 64) g_barG[i] = 0u;
}

// ---------------------------------------------------------------------------
// fp16 m16n8k16 MMA, fp32 accumulate
// ---------------------------------------------------------------------------
#define MMAF16(d, a0, a1, a2, a3, b0, b1)                                     \
    asm volatile("mma.sync.aligned.m16n8k16.row.col.f32.f16.f16.f32 "        \
                 "{%0,%1,%2,%3}, {%4,%5,%6,%7}, {%8,%9}, {%0,%1,%2,%3};"     \
                 : "+f"(d[0]), "+f"(d[1]), "+f"(d[2]), "+f"(d[3])            \
                 : "r"(a0), "r"(a1), "r"(a2), "r"(a3), "r"(b0), "r"(b1))

#define MMA_K32(acc, A0, A1, Bv)                                              \
    do {                                                                      \
        MMAF16(acc, A0.x, A1.x, A0.y, A1.y, Bv.x, Bv.y);                      \
        MMAF16(acc, A0.z, A1.z, A0.w, A1.w, Bv.z, Bv.w);                      \
    } while (0)

// ---------------------------------------------------------------------------
// SMEM-staged phase GEMMs (byte-identical to R11..R14-passing)
// ---------------------------------------------------------------------------
template<int K, int MODE>
__global__ __launch_bounds__(256, 1) void mma_gemm_s(const float* __restrict__ bias0,
                                                     const float* __restrict__ bias1)
{
    extern __shared__ char sm[];
    const __half* __restrict__ gA = MODE ? g_x : g_f;
    const __half* __restrict__ gB = MODE ? g_Wi : g_Wp;

    const int tid = threadIdx.x, w = tid >> 5, lane = tid & 31;
    const int mw = w & 1, nw = w >> 1;
    const int r = lane >> 2, c = lane & 3;
    const int m0 = blockIdx.y * 128, n0 = blockIdx.x * 128;
    const uint32_t sbase = cvta_smem(sm);

    auto stage = [&](int q, int buf) {
        const size_t gk = (size_t)q * 32;
#pragma unroll
        for (int t = 0; t < 4; t++) {
            int i = tid + t * 256;
            int plane = i >> 9, o = i & 511, row = o >> 2, seg = o & 3;
            const __half* gp = plane ? gB : gA;
            int grow = (plane ? n0 : m0) + row;
            const __half* src = gp + (size_t)grow * K + gk + seg * 8;
            uint32_t dst = sbase + (uint32_t)(buf * 16384 + plane * 8192 +
                                              row * 64 + seg * 16);
            asm volatile("cp.async.cg.shared.global [%0], [%1], 16;"
                         :: "r"(dst), "l"(__cvta_generic_to_global(src)));
        }
        asm volatile("cp.async.commit_group;" ::: "memory");
    };

    float acc[4][4][4];
#pragma unroll
    for (int i = 0; i < 4; i++)
#pragma unroll
        for (int j = 0; j < 4; j++)
#pragma unroll
            for (int q = 0; q < 4; q++) acc[i][j][q] = 0.f;

    const int NK = K / 32;
    stage(0, 0);

    for (int q = 0; q < NK; q++) {
        asm volatile("cp.async.wait_group 0;" ::: "memory");
        __syncthreads();
        if (q + 1 < NK) stage(q + 1, (q + 1) & 1);

        const char* bufp = sm + (q & 1) * 16384;
        const uint4* A = reinterpret_cast<const uint4*>(bufp);
        const uint4* Bv = reinterpret_cast<const uint4*>(bufp + 8192);

        uint4 bf[4];
#pragma unroll
        for (int j = 0; j < 4; j++) {
            int row = nw * 32 + j * 8 + r;
            bf[j] = Bv[row * 4 + c];
        }
#pragma unroll
        for (int i = 0; i < 4; i++) {
            int row0 = mw * 64 + i * 16 + r;
            uint4 a0 = A[row0 * 4 + c];
            uint4 a1 = A[(row0 + 8) * 4 + c];
#pragma unroll
            for (int j = 0; j < 4; j++)
                MMA_K32(acc[i][j], a0, a1, bf[j]);
        }
        __syncthreads();
    }

#pragma unroll
    for (int i = 0; i < 4; i++) {
#pragma unroll
        for (int h = 0; h < 2; h++) {
            int m = m0 + mw * 64 + i * 16 + r + h * 8;
            if (MODE == 0) {
                int ngrp = n0 + nw * 32;
                uint32_t hp[4];
#pragma unroll
                for (int j = 0; j < 4; j++) {
                    int n = ngrp + j * 8 + 2 * c;
                    float v0 = fmaxf(acc[i][j][2 * h]     + bias0[n],     0.f);
                    float v1 = fmaxf(acc[i][j][2 * h + 1] + bias0[n + 1], 0.f);
                    __half2 hh = __floats2half2_rn(v0, v1);
                    hp[j] = *reinterpret_cast<uint32_t*>(&hh);
                }
                int nidx0 = ngrp + 8 * c;
                *reinterpret_cast<uint4*>(g_x + (size_t)m * I_ + nidx0) =
                    make_uint4(hp[0], hp[1], hp[2], hp[3]);
            } else {
                int bb = m >> 9, tt = m & 511;
                float* op = g_gx + ((size_t)tt * B_ + bb) * G4;
#pragma unroll
                for (int j = 0; j < 4; j++) {
                    int n = n0 + nw * 32 + j * 8 + 2 * c;
                    float2 o;
                    o.x = acc[i][j][2 * h]     + bias0[n]     + bias1[n];
                    o.y = acc[i][j][2 * h + 1] + bias0[n + 1] + bias1[n + 1];
                    *reinterpret_cast<float2*>(op + n) = o;
                }
            }
        }
    }
}

// ---------------------------------------------------------------------------
// Persistent recurrence. Two INDEPENDENT barrier groups (one per batch half):
// block (s,nb) reads/writes h only in half nb, so cross-half sync is never
// needed. Arrival via red.release.gpu; poll via ld.acquire.gpu (no MEMBAR).
// ---------------------------------------------------------------------------
__device__ __forceinline__ float sigf(float x) { return 1.f / (1.f + expf(-x)); }

__device__ __forceinline__ void grid_bar_g(unsigned* cnt, unsigned target) {
    __syncthreads();
    if (threadIdx.x == 0) {
        asm volatile("red.release.gpu.global.add.u32 [%0], %1;"
                     :: "l"(cnt), "r"(1u) : "memory");
        unsigned v, ns = 4;
        while (true) {
            asm volatile("ld.acquire.gpu.global.u32 %0, [%1];"
                         : "=r"(v) : "l"(cnt));
            if (v >= target) break;
            __nanosleep(ns);
            if (ns < 64) ns <<= 1;
        }
    }
    __syncthreads();
}

__global__ __launch_bounds__(256, 1) void lstm_persist(float* __restrict__ out,
                                                       const float* __restrict__ b_cls)
{
    const int blk = blockIdx.x;
    const bool is_cls = blk >= 128;
    const int s  = is_cls ? 64 : (blk >> 1);
    const int nb = is_cls ? (blk - 128) : (blk & 1);
    const int tid = threadIdx.x, w = tid >> 5, lane = tid & 31;
    const int mw = w & 3, nw = w >> 2;
    const int r = lane >> 2, c = lane & 3;
    const int m0 = s * 64 + mw * 16;
    const int bb0 = nb * 32 + nw * 16;
    unsigned* bar = &g_barG[nb * 32];      // group counter (128B apart)

    __shared__ float Ds[64][33];
    __shared__ float cs[32][16];
    if (!is_cls)
        for (int e = tid; e < 512; e += 256) cs[e >> 4][e & 15] = 0.f;

    // epilogue coordinates (pair-based)
    const int eb = tid >> 3, epr = tid & 7;        // batch-in-half, k-pair
    const int ebatch = nb * 32 + eb;
    const int ek = s * 16 + 2 * epr;
    const int ehidx = (ek & ~31) + permPair(ek & 31);

    const __half* pA = g_Wr + (size_t)(m0 + r) * I_ + c * 8;
    const size_t A8 = (size_t)8 * I_;

    for (int t = 0; t <= T_; t++) {
        grid_bar_g(bar, (unsigned)(t + 1) * GRP);
        const bool active = is_cls ? (t >= 1) : (t < T_);
        if (!active) continue;
        const int p = t & 1;

        // gx register prefetch (gate blocks only) — hides DRAM latency under MMA
        float2 gxv[4];
        if (!is_cls) {
            const float* gxp = g_gx + ((size_t)t * B_ + ebatch) * G4 + s * 16 + 2 * epr;
#pragma unroll
            for (int g = 0; g < 4; g++)
                gxv[g] = ld_cg_f2(gxp + g * 1024);
        }

        const __half* pB = g_h[p] + (size_t)(bb0 + r) * I_ + c * 8;

        float accA[2][4], accB[2][4];
#pragma unroll
        for (int j = 0; j < 2; j++)
#pragma unroll
            for (int q = 0; q < 4; q++) { accA[j][q] = 0.f; accB[j][q] = 0.f; }

#pragma unroll 4
        for (int q = 0; q < 16; q++) {
            int offA = q * 32, offB = (q + 16) * 32;
            uint4 a0A = *reinterpret_cast<const uint4*>(pA + offA);
            uint4 a1A = *reinterpret_cast<const uint4*>(pA + A8 + offA);
            uint4 a0B = *reinterpret_cast<const uint4*>(pA + offB);
            uint4 a1B = *reinterpret_cast<const uint4*>(pA + A8 + offB);
#pragma unroll
            for (int j = 0; j < 2; j++) {
                uint4 bvA = ld_cg_u4(pB + (size_t)j * A8 + offA);
                uint4 bvB = ld_cg_u4(pB + (size_t)j * A8 + offB);
                MMA_K32(accA[j], a0A, a1A, bvA);
                MMA_K32(accB[j], a0B, a1B, bvB);
            }
        }
        float acc[2][4];
#pragma unroll
        for (int j = 0; j < 2; j++)
#pragma unroll
            for (int q = 0; q < 4; q++) acc[j][q] = accA[j][q] + accB[j][q];

        if (is_cls) {
            int tq = t - 1;
#pragma unroll
            for (int j = 0; j < 2; j++) {
                int bA = bb0 + j * 8 + 2 * c;
                int row0 = mw * 16 + r, row1 = row0 + 8;
                if (row0 < NC) {
                    float bc = b_cls[row0];
                    out[((size_t)bA       * T_ + tq) * NC + row0] = acc[j][0] + bc;
                    out[((size_t)(bA + 1) * T_ + tq) * NC + row0] = acc[j][1] + bc;
                }
                if (row1 < NC) {
                    float bc = b_cls[row1];
                    out[((size_t)bA       * T_ + tq) * NC + row1] = acc[j][2] + bc;
                    out[((size_t)(bA + 1) * T_ + tq) * NC + row1] = acc[j][3] + bc;
                }
            }
            continue;
        }

#pragma unroll
        for (int j = 0; j < 2; j++) {
            int col = nw * 16 + j * 8 + 2 * c;
            Ds[mw * 16 + r    ][col    ] = acc[j][0];
            Ds[mw * 16 + r    ][col + 1] = acc[j][1];
            Ds[mw * 16 + r + 8][col    ] = acc[j][2];
            Ds[mw * 16 + r + 8][col + 1] = acc[j][3];
        }
        __syncthreads();

        // fused cell update, one k-pair per thread; half2 h store
        {
            int u0 = 2 * epr, u1 = u0 + 1;
            float gi0 = Ds[u0][eb]      + gxv[0].x;
            float gi1 = Ds[u1][eb]      + gxv[0].y;
            float gf0 = Ds[16 + u0][eb] + gxv[1].x;
            float gf1 = Ds[16 + u1][eb] + gxv[1].y;
            float gg0 = Ds[32 + u0][eb] + gxv[2].x;
            float gg1 = Ds[32 + u1][eb] + gxv[2].y;
            float go0 = Ds[48 + u0][eb] + gxv[3].x;
            float go1 = Ds[48 + u1][eb] + gxv[3].y;
            float cn0 = sigf(gf0) * cs[eb][u0] + sigf(gi0) * tanhf(gg0);
            float cn1 = sigf(gf1) * cs[eb][u1] + sigf(gi1) * tanhf(gg1);
            cs[eb][u0] = cn0;
            cs[eb][u1] = cn1;
            __half2 hv = __floats2half2_rn(sigf(go0) * tanhf(cn0),
                                           sigf(go1) * tanhf(cn1));
            st_cg_u32(&g_h[(t + 1) & 1][(size_t)ebatch * I_ + ehidx],
                      *reinterpret_cast<uint32_t*>(&hv));
        }
        __syncthreads();   // cs/Ds reuse safety before next iteration
    }
}

// ---------------------------------------------------------------------------
extern "C" void kernel_launch(void* const* d_in, const int* in_sizes, int n_in,
                              void* d_out, int out_size)
{
    (void)in_sizes; (void)n_in; (void)out_size;
    const float* feat  = (const float*)d_in[0];
    const float* W_pre = (const float*)d_in[1];
    const float* b_pre = (const float*)d_in[2];
    const float* W_ih  = (const float*)d_in[3];
    const float* b_ih  = (const float*)d_in[4];
    const float* W_hh  = (const float*)d_in[5];
    const float* b_hh  = (const float*)d_in[6];
    const float* W_cls = (const float*)d_in[7];
    const float* b_cls = (const float*)d_in[8];
    float* out = (float*)d_out;

    const int SMEM_DYN = 2 * 16384;

    prep_split<0><<<dim3(F_ / 512, M_), 256>>>(feat,  F_);
    prep_split<1><<<dim3(F_ / 512, I_), 256>>>(W_pre, F_);
    prep_split<2><<<dim3(I_ / 512, G4), 256>>>(W_ih,  I_);

    // Phase 1: x = relu(feat @ W_pre^T + b_pre)      M=32768 N=1024 K=3072
    mma_gemm_s<F_, 0><<<dim3(1024 / 128, M_ / 128), 256, SMEM_DYN>>>(b_pre, nullptr);

    prep_rec<<<dim3(I_ / 512, MP), 256>>>(W_hh, W_cls);
    init_state<<<(B_ * I_ + 255) / 256, 256>>>();

    // Phase 2: gx[t][b] = x @ W_ih^T + b_ih + b_hh   M=32768 N=4096 K=1024
    mma_gemm_s<I_, 1><<<dim3(G4 / 128, M_ / 128), 256, SMEM_DYN>>>(b_ih, b_hh);

    // Phase 3: full recurrence in ONE persistent kernel (513 rounds,
    // two independent 65-block barrier groups)
    lstm_persist<<<NBLK, 256>>>(out, b_cls);
}

// round 16
// speedup vs baseline: 2.1054x; 1.0608x over previous
#include <cuda_runtime.h>
#include <cuda_fp16.h>
#include <math.h>
#include <stdint.h>

#define B_  64
#define T_  512
#define F_  3072
#define I_  1024
#define G4  4096
#define NC  22
#define M_  (B_*T_)     /* 32768 */
#define MP  4160        /* recurrent W'' rows: 4096 gates + 22 cls + pad */
#define NBLK 130        /* persistent grid */
#define GRP  65         /* blocks per barrier group (one batch half) */
#define SROW 2112       /* padded SMEM row stride for staged h (bank-safe) */

// ---------------------------------------------------------------------------
// Scratch (__device__ globals; referenced ONLY from device code — R5 lesson)
// ---------------------------------------------------------------------------
__device__ __half g_f[(size_t)M_ * F_];      // features fp16, k-permuted
__device__ __half g_x[(size_t)M_ * I_];      // relu(pre) out fp16, k-permuted
__device__ float  g_gx[(size_t)T_ * B_ * G4];// gate-input precompute [t][b][4096]
__device__ __half g_Wp[(size_t)I_ * F_];
__device__ __half g_Wi[(size_t)G4 * I_];
__device__ __half g_Wr[(size_t)MP * I_];     // re-tiled [Whh;Wcls;0], k-permuted
__device__ __half g_h[2][B_ * I_];           // h fp16, double buffered, permuted
__device__ unsigned g_barG[64];              // 2 group counters, 128B apart

// k-permutation within a 32-group: lane quad c's 8 needed fp16 are contiguous.
__device__ __forceinline__ int perm32(int p) {
    return (((p & 7) >> 1) << 3) + ((p >> 3) << 1) + (p & 1);
}
__device__ __forceinline__ int permPair(int p) {   // p even
    return (((p & 7) >> 1) << 3) + ((p >> 3) << 1);
}
__device__ __forceinline__ uint32_t cvta_smem(const void* p) {
    uint32_t a;
    asm("{ .reg .u64 t; cvta.to.shared.u64 t, %1; cvt.u32.u64 %0, t; }"
        : "=r"(a) : "l"(p));
    return a;
}
__device__ __forceinline__ float2 ld_cg_f2(const float* p) {
    float2 v;
    asm volatile("ld.global.cg.v2.f32 {%0,%1}, [%2];"
                 : "=f"(v.x), "=f"(v.y) : "l"(p));
    return v;
}
__device__ __forceinline__ void st_cg_u32(void* p, uint32_t v) {
    asm volatile("st.global.cg.u32 [%0], %1;" :: "l"(p), "r"(v) : "memory");
}
#define LDS128U(v, addr)                                                      \
    asm volatile("ld.shared.v4.u32 {%0,%1,%2,%3}, [%4];"                     \
                 : "=r"(v.x), "=r"(v.y), "=r"(v.z), "=r"(v.w) : "r"(addr))

// ---------------------------------------------------------------------------
// Prep kernels (byte-identical to R11..R15-passing)
// ---------------------------------------------------------------------------
template<int SEL>
__global__ void prep_split(const float* __restrict__ src, int K)
{
    __half* __restrict__ dst = (SEL == 0) ? g_f : (SEL == 1) ? g_Wp : g_Wi;
    int row = blockIdx.y;
    int k = (blockIdx.x * 256 + threadIdx.x) * 2;
    float2 v = *reinterpret_cast<const float2*>(src + (size_t)row * K + k);
    int idx = (k & ~31) + permPair(k & 31);
    *reinterpret_cast<__half2*>(dst + (size_t)row * K + idx) =
        __floats2half2_rn(v.x, v.y);
}

__global__ void prep_rec(const float* __restrict__ W_hh,
                         const float* __restrict__ W_cls)
{
    int m = blockIdx.y;
    int k = (blockIdx.x * 256 + threadIdx.x) * 2;
    float2 v = make_float2(0.f, 0.f);
    if (m < 4096) {
        int s = m >> 6, loc = m & 63, g = loc >> 4, u = loc & 15;
        v = *reinterpret_cast<const float2*>(
            W_hh + (size_t)(g * 1024 + s * 16 + u) * I_ + k);
    } else if (m < 4096 + NC) {
        v = *reinterpret_cast<const float2*>(W_cls + (size_t)(m - 4096) * I_ + k);
    }
    int idx = (k & ~31) + permPair(k & 31);
    *reinterpret_cast<__half2*>(g_Wr + (size_t)m * I_ + idx) =
        __floats2half2_rn(v.x, v.y);
}

__global__ void init_state() {
    int i = blockIdx.x * blockDim.x + threadIdx.x;
    if (i < B_ * I_) g_h[0][i] = __float2half(0.f);
    if (i < 64) g_barG[i] = 0u;
}

// ---------------------------------------------------------------------------
// fp16 m16n8k16 MMA, fp32 accumulate
// ---------------------------------------------------------------------------
#define MMAF16(d, a0, a1, a2, a3, b0, b1)                                     \
    asm volatile("mma.sync.aligned.m16n8k16.row.col.f32.f16.f16.f32 "        \
                 "{%0,%1,%2,%3}, {%4,%5,%6,%7}, {%8,%9}, {%0,%1,%2,%3};"     \
                 : "+f"(d[0]), "+f"(d[1]), "+f"(d[2]), "+f"(d[3])            \
                 : "r"(a0), "r"(a1), "r"(a2), "r"(a3), "r"(b0), "r"(b1))

#define MMA_K32(acc, A0, A1, Bv)                                              \
    do {                                                                      \
        MMAF16(acc, A0.x, A1.x, A0.y, A1.y, Bv.x, Bv.y);                      \
        MMAF16(acc, A0.z, A1.z, A0.w, A1.w, Bv.z, Bv.w);                      \
    } while (0)

// ---------------------------------------------------------------------------
// SMEM-staged phase GEMMs (byte-identical to R11..R15-passing)
// ---------------------------------------------------------------------------
template<int K, int MODE>
__global__ __launch_bounds__(256, 1) void mma_gemm_s(const float* __restrict__ bias0,
                                                     const float* __restrict__ bias1)
{
    extern __shared__ char sm[];
    const __half* __restrict__ gA = MODE ? g_x : g_f;
    const __half* __restrict__ gB = MODE ? g_Wi : g_Wp;

    const int tid = threadIdx.x, w = tid >> 5, lane = tid & 31;
    const int mw = w & 1, nw = w >> 1;
    const int r = lane >> 2, c = lane & 3;
    const int m0 = blockIdx.y * 128, n0 = blockIdx.x * 128;
    const uint32_t sbase = cvta_smem(sm);

    auto stage = [&](int q, int buf) {
        const size_t gk = (size_t)q * 32;
#pragma unroll
        for (int t = 0; t < 4; t++) {
            int i = tid + t * 256;
            int plane = i >> 9, o = i & 511, row = o >> 2, seg = o & 3;
            const __half* gp = plane ? gB : gA;
            int grow = (plane ? n0 : m0) + row;
            const __half* src = gp + (size_t)grow * K + gk + seg * 8;
            uint32_t dst = sbase + (uint32_t)(buf * 16384 + plane * 8192 +
                                              row * 64 + seg * 16);
            asm volatile("cp.async.cg.shared.global [%0], [%1], 16;"
                         :: "r"(dst), "l"(__cvta_generic_to_global(src)));
        }
        asm volatile("cp.async.commit_group;" ::: "memory");
    };

    float acc[4][4][4];
#pragma unroll
    for (int i = 0; i < 4; i++)
#pragma unroll
        for (int j = 0; j < 4; j++)
#pragma unroll
            for (int q = 0; q < 4; q++) acc[i][j][q] = 0.f;

    const int NK = K / 32;
    stage(0, 0);

    for (int q = 0; q < NK; q++) {
        asm volatile("cp.async.wait_group 0;" ::: "memory");
        __syncthreads();
        if (q + 1 < NK) stage(q + 1, (q + 1) & 1);

        const char* bufp = sm + (q & 1) * 16384;
        const uint4* A = reinterpret_cast<const uint4*>(bufp);
        const uint4* Bv = reinterpret_cast<const uint4*>(bufp + 8192);

        uint4 bf[4];
#pragma unroll
        for (int j = 0; j < 4; j++) {
            int row = nw * 32 + j * 8 + r;
            bf[j] = Bv[row * 4 + c];
        }
#pragma unroll
        for (int i = 0; i < 4; i++) {
            int row0 = mw * 64 + i * 16 + r;
            uint4 a0 = A[row0 * 4 + c];
            uint4 a1 = A[(row0 + 8) * 4 + c];
#pragma unroll
            for (int j = 0; j < 4; j++)
                MMA_K32(acc[i][j], a0, a1, bf[j]);
        }
        __syncthreads();
    }

#pragma unroll
    for (int i = 0; i < 4; i++) {
#pragma unroll
        for (int h = 0; h < 2; h++) {
            int m = m0 + mw * 64 + i * 16 + r + h * 8;
            if (MODE == 0) {
                int ngrp = n0 + nw * 32;
                uint32_t hp[4];
#pragma unroll
                for (int j = 0; j < 4; j++) {
                    int n = ngrp + j * 8 + 2 * c;
                    float v0 = fmaxf(acc[i][j][2 * h]     + bias0[n],     0.f);
                    float v1 = fmaxf(acc[i][j][2 * h + 1] + bias0[n + 1], 0.f);
                    __half2 hh = __floats2half2_rn(v0, v1);
                    hp[j] = *reinterpret_cast<uint32_t*>(&hh);
                }
                int nidx0 = ngrp + 8 * c;
                *reinterpret_cast<uint4*>(g_x + (size_t)m * I_ + nidx0) =
                    make_uint4(hp[0], hp[1], hp[2], hp[3]);
            } else {
                int bb = m >> 9, tt = m & 511;
                float* op = g_gx + ((size_t)tt * B_ + bb) * G4;
#pragma unroll
                for (int j = 0; j < 4; j++) {
                    int n = n0 + nw * 32 + j * 8 + 2 * c;
                    float2 o;
                    o.x = acc[i][j][2 * h]     + bias0[n]     + bias1[n];
                    o.y = acc[i][j][2 * h + 1] + bias0[n + 1] + bias1[n + 1];
                    *reinterpret_cast<float2*>(op + n) = o;
                }
            }
        }
    }
}

// ---------------------------------------------------------------------------
// Persistent recurrence. Per step: gx prefetch (pre-barrier) -> group barrier
// -> h staged to SMEM via 2 pipelined cp.async halves -> MMA from LDS ->
// cell -> half2 h store. Two independent 65-block barrier groups.
// ---------------------------------------------------------------------------
__device__ __forceinline__ float sigf(float x) { return 1.f / (1.f + expf(-x)); }

__device__ __forceinline__ void grid_bar_g(unsigned* cnt, unsigned target) {
    __syncthreads();
    if (threadIdx.x == 0) {
        asm volatile("red.release.gpu.global.add.u32 [%0], %1;"
                     :: "l"(cnt), "r"(1u) : "memory");
        unsigned v, ns = 4;
        while (true) {
            asm volatile("ld.acquire.gpu.global.u32 %0, [%1];"
                         : "=r"(v) : "l"(cnt));
            if (v >= target) break;
            __nanosleep(ns);
            if (ns < 64) ns <<= 1;
        }
    }
    __syncthreads();
}

__global__ __launch_bounds__(256, 1) void lstm_persist(float* __restrict__ out,
                                                       const float* __restrict__ b_cls)
{
    extern __shared__ char hs[];                // staged h: 32 rows x SROW
    const int blk = blockIdx.x;
    const bool is_cls = blk >= 128;
    const int s  = is_cls ? 64 : (blk >> 1);
    const int nb = is_cls ? (blk - 128) : (blk & 1);
    const int tid = threadIdx.x, w = tid >> 5, lane = tid & 31;
    const int mw = w & 3, nw = w >> 2;
    const int r = lane >> 2, c = lane & 3;
    const int m0 = s * 64 + mw * 16;
    unsigned* bar = &g_barG[nb * 32];
    const uint32_t hsb = cvta_smem(hs);

    __shared__ float Ds[64][33];
    __shared__ float cs[32][16];
    if (!is_cls)
        for (int e = tid; e < 512; e += 256) cs[e >> 4][e & 15] = 0.f;

    // epilogue coordinates (pair-based)
    const int eb = tid >> 3, epr = tid & 7;        // batch-in-half, k-pair
    const int ebatch = nb * 32 + eb;
    const int ek = s * 16 + 2 * epr;
    const int ehidx = (ek & ~31) + permPair(ek & 31);

    const __half* pA = g_Wr + (size_t)(m0 + r) * I_ + c * 8;
    const size_t A8 = (size_t)8 * I_;
    // SMEM fragment addresses: local rows nw*16+r (+8 for j=1); col c*16 bytes
    const uint32_t sB0 = hsb + (uint32_t)(nw * 16 + r) * SROW + (uint32_t)c * 16;
    const uint32_t sB1 = sB0 + 8 * SROW;

    for (int t = 0; t <= T_; t++) {
        const bool active = is_cls ? (t >= 1) : (t < T_);

        // gx prefetch BEFORE the barrier (gx has no h dependency)
        float2 gxv[4];
        if (!is_cls && t < T_) {
            const float* gxp = g_gx + ((size_t)t * B_ + ebatch) * G4 + s * 16 + 2 * epr;
#pragma unroll
            for (int g = 0; g < 4; g++)
                gxv[g] = ld_cg_f2(gxp + g * 1024);
        }

        grid_bar_g(bar, (unsigned)(t + 1) * GRP);
        if (!active) continue;
        const int p = t & 1;

        // stage this half's 32x2048B h rows into SMEM (two column halves)
        const char* hsrc = (const char*)(g_h[p] + (size_t)nb * 32 * I_);
#pragma unroll
        for (int half = 0; half < 2; half++) {
#pragma unroll
            for (int u = 0; u < 8; u++) {
                int i = tid + u * 256;                 // 0..2047
                int row = i >> 6, seg = (i & 63) + half * 64;
                const char* src = hsrc + row * 2048 + seg * 16;
                uint32_t dst = hsb + (uint32_t)(row * SROW + seg * 16);
                asm volatile("cp.async.cg.shared.global [%0], [%1], 16;"
                             :: "r"(dst), "l"(__cvta_generic_to_global(src)));
            }
            asm volatile("cp.async.commit_group;" ::: "memory");
        }

        float accA[2][4], accB[2][4];
#pragma unroll
        for (int j = 0; j < 2; j++)
#pragma unroll
            for (int q = 0; q < 4; q++) { accA[j][q] = 0.f; accB[j][q] = 0.f; }

        // wait for column-half 0; MMA on it while half 1 streams in
        asm volatile("cp.async.wait_group 1;" ::: "memory");
        __syncthreads();
#pragma unroll 4
        for (int q = 0; q < 16; q++) {
            int offA = q * 32;
            uint4 a0 = *reinterpret_cast<const uint4*>(pA + offA);
            uint4 a1 = *reinterpret_cast<const uint4*>(pA + A8 + offA);
            uint4 b0, b1;
            LDS128U(b0, sB0 + q * 64);
            LDS128U(b1, sB1 + q * 64);
            MMA_K32(accA[0], a0, a1, b0);
            MMA_K32(accA[1], a0, a1, b1);
        }
        asm volatile("cp.async.wait_group 0;" ::: "memory");
        __syncthreads();
#pragma unroll 4
        for (int q = 0; q < 16; q++) {
            int offB = (q + 16) * 32;
            uint4 a0 = *reinterpret_cast<const uint4*>(pA + offB);
            uint4 a1 = *reinterpret_cast<const uint4*>(pA + A8 + offB);
            uint4 b0, b1;
            LDS128U(b0, sB0 + 1024 + q * 64);
            LDS128U(b1, sB1 + 1024 + q * 64);
            MMA_K32(accB[0], a0, a1, b0);
            MMA_K32(accB[1], a0, a1, b1);
        }

        float acc[2][4];
#pragma unroll
        for (int j = 0; j < 2; j++)
#pragma unroll
            for (int q = 0; q < 4; q++) acc[j][q] = accA[j][q] + accB[j][q];

        if (is_cls) {
            int tq = t - 1;
#pragma unroll
            for (int j = 0; j < 2; j++) {
                int bA = nb * 32 + nw * 16 + j * 8 + 2 * c;
                int row0 = mw * 16 + r, row1 = row0 + 8;
                if (row0 < NC) {
                    float bc = b_cls[row0];
                    out[((size_t)bA       * T_ + tq) * NC + row0] = acc[j][0] + bc;
                    out[((size_t)(bA + 1) * T_ + tq) * NC + row0] = acc[j][1] + bc;
                }
                if (row1 < NC) {
                    float bc = b_cls[row1];
                    out[((size_t)bA       * T_ + tq) * NC + row1] = acc[j][2] + bc;
                    out[((size_t)(bA + 1) * T_ + tq) * NC + row1] = acc[j][3] + bc;
                }
            }
            continue;
        }

#pragma unroll
        for (int j = 0; j < 2; j++) {
            int col = nw * 16 + j * 8 + 2 * c;
            Ds[mw * 16 + r    ][col    ] = acc[j][0];
            Ds[mw * 16 + r    ][col + 1] = acc[j][1];
            Ds[mw * 16 + r + 8][col    ] = acc[j][2];
            Ds[mw * 16 + r + 8][col + 1] = acc[j][3];
        }
        __syncthreads();

        // fused cell update, one k-pair per thread; half2 h store
        {
            int u0 = 2 * epr, u1 = u0 + 1;
            float gi0 = Ds[u0][eb]      + gxv[0].x;
            float gi1 = Ds[u1][eb]      + gxv[0].y;
            float gf0 = Ds[16 + u0][eb] + gxv[1].x;
            float gf1 = Ds[16 + u1][eb] + gxv[1].y;
            float gg0 = Ds[32 + u0][eb] + gxv[2].x;
            float gg1 = Ds[32 + u1][eb] + gxv[2].y;
            float go0 = Ds[48 + u0][eb] + gxv[3].x;
            float go1 = Ds[48 + u1][eb] + gxv[3].y;
            float cn0 = sigf(gf0) * cs[eb][u0] + sigf(gi0) * tanhf(gg0);
            float cn1 = sigf(gf1) * cs[eb][u1] + sigf(gi1) * tanhf(gg1);
            cs[eb][u0] = cn0;
            cs[eb][u1] = cn1;
            __half2 hv = __floats2half2_rn(sigf(go0) * tanhf(cn0),
                                           sigf(go1) * tanhf(cn1));
            st_cg_u32(&g_h[(t + 1) & 1][(size_t)ebatch * I_ + ehidx],
                      *reinterpret_cast<uint32_t*>(&hv));
        }
        __syncthreads();   // cs/Ds reuse safety before next iteration
    }
}

// ---------------------------------------------------------------------------
extern "C" void kernel_launch(void* const* d_in, const int* in_sizes, int n_in,
                              void* d_out, int out_size)
{
    (void)in_sizes; (void)n_in; (void)out_size;
    const float* feat  = (const float*)d_in[0];
    const float* W_pre = (const float*)d_in[1];
    const float* b_pre = (const float*)d_in[2];
    const float* W_ih  = (const float*)d_in[3];
    const float* b_ih  = (const float*)d_in[4];
    const float* W_hh  = (const float*)d_in[5];
    const float* b_hh  = (const float*)d_in[6];
    const float* W_cls = (const float*)d_in[7];
    const float* b_cls = (const float*)d_in[8];
    float* out = (float*)d_out;

    const int SMEM_DYN  = 2 * 16384;
    const int SMEM_PERS = 32 * SROW;            // 67584 B staged h
    static bool attr_done = false;
    if (!attr_done) {
        cudaFuncSetAttribute(lstm_persist,
                             cudaFuncAttributeMaxDynamicSharedMemorySize, SMEM_PERS);
        attr_done = true;
    }

    prep_split<0><<<dim3(F_ / 512, M_), 256>>>(feat,  F_);
    prep_split<1><<<dim3(F_ / 512, I_), 256>>>(W_pre, F_);
    prep_split<2><<<dim3(I_ / 512, G4), 256>>>(W_ih,  I_);

    // Phase 1: x = relu(feat @ W_pre^T + b_pre)      M=32768 N=1024 K=3072
    mma_gemm_s<F_, 0><<<dim3(1024 / 128, M_ / 128), 256, SMEM_DYN>>>(b_pre, nullptr);

    prep_rec<<<dim3(I_ / 512, MP), 256>>>(W_hh, W_cls);
    init_state<<<(B_ * I_ + 255) / 256, 256>>>();

    // Phase 2: gx[t][b] = x @ W_ih^T + b_ih + b_hh   M=32768 N=4096 K=1024
    mma_gemm_s<I_, 1><<<dim3(G4 / 128, M_ / 128), 256, SMEM_DYN>>>(b_ih, b_hh);

    // Phase 3: full recurrence in ONE persistent kernel (513 rounds,
    // two independent 65-block barrier groups, h staged via cp.async)
    lstm_persist<<<NBLK, 256, SMEM_PERS>>>(out, b_cls);
}

// round 17
// speedup vs baseline: 2.2925x; 1.0889x over previous
#include <cuda_runtime.h>
#include <cuda_fp16.h>
#include <math.h>
#include <stdint.h>

#define B_  64
#define T_  512
#define F_  3072
#define I_  1024
#define G4  4096
#define NC  22
#define M_  (B_*T_)     /* 32768 */
#define MP  4160        /* recurrent W'' rows: 4096 gates + 22 cls + pad */
#define NBLK 130        /* persistent grid */
#define GRP  65         /* blocks per barrier group (one batch half) */
#define SROW 2112       /* padded SMEM row stride for staged h (bank-safe) */

// ---------------------------------------------------------------------------
// Scratch (__device__ globals; referenced ONLY from device code — R5 lesson)
// ---------------------------------------------------------------------------
__device__ __half g_f[(size_t)M_ * F_];      // features fp16, k-permuted
__device__ __half g_x[(size_t)M_ * I_];      // relu(pre) out fp16, k-permuted
__device__ float  g_gx[(size_t)T_ * B_ * G4];// gate-input precompute [t][b][4096]
__device__ __half g_Wp[(size_t)I_ * F_];
__device__ __half g_Wi[(size_t)G4 * I_];
__device__ __half g_Wr[(size_t)MP * I_];     // re-tiled [Whh;Wcls;0], k-permuted
__device__ __half g_h[2][B_ * I_];           // h fp16, double buffered, permuted
__device__ unsigned g_barG[64];              // 2 group counters, 128B apart

// k-permutation within a 32-group: lane quad c's 8 needed fp16 are contiguous.
__device__ __forceinline__ int perm32(int p) {
    return (((p & 7) >> 1) << 3) + ((p >> 3) << 1) + (p & 1);
}
__device__ __forceinline__ int permPair(int p) {   // p even
    return (((p & 7) >> 1) << 3) + ((p >> 3) << 1);
}
__device__ __forceinline__ uint32_t cvta_smem(const void* p) {
    uint32_t a;
    asm("{ .reg .u64 t; cvta.to.shared.u64 t, %1; cvt.u32.u64 %0, t; }"
        : "=r"(a) : "l"(p));
    return a;
}
__device__ __forceinline__ float2 ld_cg_f2(const float* p) {
    float2 v;
    asm volatile("ld.global.cg.v2.f32 {%0,%1}, [%2];"
                 : "=f"(v.x), "=f"(v.y) : "l"(p));
    return v;
}
__device__ __forceinline__ void st_cg_u32(void* p, uint32_t v) {
    asm volatile("st.global.cg.u32 [%0], %1;" :: "l"(p), "r"(v) : "memory");
}
#define LDS128U(v, addr)                                                      \
    asm volatile("ld.shared.v4.u32 {%0,%1,%2,%3}, [%4];"                     \
                 : "=r"(v.x), "=r"(v.y), "=r"(v.z), "=r"(v.w) : "r"(addr))

// ---------------------------------------------------------------------------
// Prep kernels (byte-identical to R11..R16-passing)
// ---------------------------------------------------------------------------
template<int SEL>
__global__ void prep_split(const float* __restrict__ src, int K)
{
    __half* __restrict__ dst = (SEL == 0) ? g_f : (SEL == 1) ? g_Wp : g_Wi;
    int row = blockIdx.y;
    int k = (blockIdx.x * 256 + threadIdx.x) * 2;
    float2 v = *reinterpret_cast<const float2*>(src + (size_t)row * K + k);
    int idx = (k & ~31) + permPair(k & 31);
    *reinterpret_cast<__half2*>(dst + (size_t)row * K + idx) =
        __floats2half2_rn(v.x, v.y);
}

__global__ void prep_rec(const float* __restrict__ W_hh,
                         const float* __restrict__ W_cls)
{
    int m = blockIdx.y;
    int k = (blockIdx.x * 256 + threadIdx.x) * 2;
    float2 v = make_float2(0.f, 0.f);
    if (m < 4096) {
        int s = m >> 6, loc = m & 63, g = loc >> 4, u = loc & 15;
        v = *reinterpret_cast<const float2*>(
            W_hh + (size_t)(g * 1024 + s * 16 + u) * I_ + k);
    } else if (m < 4096 + NC) {
        v = *reinterpret_cast<const float2*>(W_cls + (size_t)(m - 4096) * I_ + k);
    }
    int idx = (k & ~31) + permPair(k & 31);
    *reinterpret_cast<__half2*>(g_Wr + (size_t)m * I_ + idx) =
        __floats2half2_rn(v.x, v.y);
}

__global__ void init_state() {
    int i = blockIdx.x * blockDim.x + threadIdx.x;
    if (i < B_ * I_) g_h[0][i] = __float2half(0.f);
    if (i < 64) g_barG[i] = 0u;
}

// ---------------------------------------------------------------------------
// fp16 m16n8k16 MMA, fp32 accumulate
// ---------------------------------------------------------------------------
#define MMAF16(d, a0, a1, a2, a3, b0, b1)                                     \
    asm volatile("mma.sync.aligned.m16n8k16.row.col.f32.f16.f16.f32 "        \
                 "{%0,%1,%2,%3}, {%4,%5,%6,%7}, {%8,%9}, {%0,%1,%2,%3};"     \
                 : "+f"(d[0]), "+f"(d[1]), "+f"(d[2]), "+f"(d[3])            \
                 : "r"(a0), "r"(a1), "r"(a2), "r"(a3), "r"(b0), "r"(b1))

#define MMA_K32(acc, A0, A1, Bv)                                              \
    do {                                                                      \
        MMAF16(acc, A0.x, A1.x, A0.y, A1.y, Bv.x, Bv.y);                      \
        MMAF16(acc, A0.z, A1.z, A0.w, A1.w, Bv.z, Bv.w);                      \
    } while (0)

// ---------------------------------------------------------------------------
// SMEM-staged phase GEMMs (byte-identical to R11..R16-passing)
// ---------------------------------------------------------------------------
template<int K, int MODE>
__global__ __launch_bounds__(256, 1) void mma_gemm_s(const float* __restrict__ bias0,
                                                     const float* __restrict__ bias1)
{
    extern __shared__ char sm[];
    const __half* __restrict__ gA = MODE ? g_x : g_f;
    const __half* __restrict__ gB = MODE ? g_Wi : g_Wp;

    const int tid = threadIdx.x, w = tid >> 5, lane = tid & 31;
    const int mw = w & 1, nw = w >> 1;
    const int r = lane >> 2, c = lane & 3;
    const int m0 = blockIdx.y * 128, n0 = blockIdx.x * 128;
    const uint32_t sbase = cvta_smem(sm);

    auto stage = [&](int q, int buf) {
        const size_t gk = (size_t)q * 32;
#pragma unroll
        for (int t = 0; t < 4; t++) {
            int i = tid + t * 256;
            int plane = i >> 9, o = i & 511, row = o >> 2, seg = o & 3;
            const __half* gp = plane ? gB : gA;
            int grow = (plane ? n0 : m0) + row;
            const __half* src = gp + (size_t)grow * K + gk + seg * 8;
            uint32_t dst = sbase + (uint32_t)(buf * 16384 + plane * 8192 +
                                              row * 64 + seg * 16);
            asm volatile("cp.async.cg.shared.global [%0], [%1], 16;"
                         :: "r"(dst), "l"(__cvta_generic_to_global(src)));
        }
        asm volatile("cp.async.commit_group;" ::: "memory");
    };

    float acc[4][4][4];
#pragma unroll
    for (int i = 0; i < 4; i++)
#pragma unroll
        for (int j = 0; j < 4; j++)
#pragma unroll
            for (int q = 0; q < 4; q++) acc[i][j][q] = 0.f;

    const int NK = K / 32;
    stage(0, 0);

    for (int q = 0; q < NK; q++) {
        asm volatile("cp.async.wait_group 0;" ::: "memory");
        __syncthreads();
        if (q + 1 < NK) stage(q + 1, (q + 1) & 1);

        const char* bufp = sm + (q & 1) * 16384;
        const uint4* A = reinterpret_cast<const uint4*>(bufp);
        const uint4* Bv = reinterpret_cast<const uint4*>(bufp + 8192);

        uint4 bf[4];
#pragma unroll
        for (int j = 0; j < 4; j++) {
            int row = nw * 32 + j * 8 + r;
            bf[j] = Bv[row * 4 + c];
        }
#pragma unroll
        for (int i = 0; i < 4; i++) {
            int row0 = mw * 64 + i * 16 + r;
            uint4 a0 = A[row0 * 4 + c];
            uint4 a1 = A[(row0 + 8) * 4 + c];
#pragma unroll
            for (int j = 0; j < 4; j++)
                MMA_K32(acc[i][j], a0, a1, bf[j]);
        }
        __syncthreads();
    }

#pragma unroll
    for (int i = 0; i < 4; i++) {
#pragma unroll
        for (int h = 0; h < 2; h++) {
            int m = m0 + mw * 64 + i * 16 + r + h * 8;
            if (MODE == 0) {
                int ngrp = n0 + nw * 32;
                uint32_t hp[4];
#pragma unroll
                for (int j = 0; j < 4; j++) {
                    int n = ngrp + j * 8 + 2 * c;
                    float v0 = fmaxf(acc[i][j][2 * h]     + bias0[n],     0.f);
                    float v1 = fmaxf(acc[i][j][2 * h + 1] + bias0[n + 1], 0.f);
                    __half2 hh = __floats2half2_rn(v0, v1);
                    hp[j] = *reinterpret_cast<uint32_t*>(&hh);
                }
                int nidx0 = ngrp + 8 * c;
                *reinterpret_cast<uint4*>(g_x + (size_t)m * I_ + nidx0) =
                    make_uint4(hp[0], hp[1], hp[2], hp[3]);
            } else {
                int bb = m >> 9, tt = m & 511;
                float* op = g_gx + ((size_t)tt * B_ + bb) * G4;
#pragma unroll
                for (int j = 0; j < 4; j++) {
                    int n = n0 + nw * 32 + j * 8 + 2 * c;
                    float2 o;
                    o.x = acc[i][j][2 * h]     + bias0[n]     + bias1[n];
                    o.y = acc[i][j][2 * h + 1] + bias0[n + 1] + bias1[n + 1];
                    *reinterpret_cast<float2*>(op + n) = o;
                }
            }
        }
    }
}

// ---------------------------------------------------------------------------
// Persistent recurrence. Per step: gx prefetch (pre-barrier) -> group barrier
// -> h staged to SMEM via 4 pipelined cp.async quarters (all issued up front)
// -> MMA from LDS -> cell -> half2 h store. Two independent barrier groups.
// ---------------------------------------------------------------------------
__device__ __forceinline__ float sigf(float x) { return 1.f / (1.f + expf(-x)); }

__device__ __forceinline__ void grid_bar_g(unsigned* cnt, unsigned target) {
    __syncthreads();
    if (threadIdx.x == 0) {
        asm volatile("red.release.gpu.global.add.u32 [%0], %1;"
                     :: "l"(cnt), "r"(1u) : "memory");
        unsigned v, ns = 4;
        while (true) {
            asm volatile("ld.acquire.gpu.global.u32 %0, [%1];"
                         : "=r"(v) : "l"(cnt));
            if (v >= target) break;
            __nanosleep(ns);
            if (ns < 64) ns <<= 1;
        }
    }
    __syncthreads();
}

__global__ __launch_bounds__(256, 1) void lstm_persist(float* __restrict__ out,
                                                       const float* __restrict__ b_cls)
{
    extern __shared__ char hs[];                // staged h: 32 rows x SROW
    const int blk = blockIdx.x;
    const bool is_cls = blk >= 128;
    const int s  = is_cls ? 64 : (blk >> 1);
    const int nb = is_cls ? (blk - 128) : (blk & 1);
    const int tid = threadIdx.x, w = tid >> 5, lane = tid & 31;
    const int mw = w & 3, nw = w >> 2;
    const int r = lane >> 2, c = lane & 3;
    const int m0 = s * 64 + mw * 16;
    unsigned* bar = &g_barG[nb * 32];
    const uint32_t hsb = cvta_smem(hs);

    __shared__ float Ds[64][33];
    __shared__ float cs[32][16];
    if (!is_cls)
        for (int e = tid; e < 512; e += 256) cs[e >> 4][e & 15] = 0.f;

    // epilogue coordinates (pair-based)
    const int eb = tid >> 3, epr = tid & 7;        // batch-in-half, k-pair
    const int ebatch = nb * 32 + eb;
    const int ek = s * 16 + 2 * epr;
    const int ehidx = (ek & ~31) + permPair(ek & 31);

    const __half* pA = g_Wr + (size_t)(m0 + r) * I_ + c * 8;
    const size_t A8 = (size_t)8 * I_;
    const uint32_t sB0 = hsb + (uint32_t)(nw * 16 + r) * SROW + (uint32_t)c * 16;
    const uint32_t sB1 = sB0 + 8 * SROW;

    // staging coords: 4 quarters x 4 segs/thread (1024 x 16B per quarter)
    const int srow = tid >> 5 | ((tid & 31) >> 5);  // placeholder; computed below

    for (int t = 0; t <= T_; t++) {
        const bool active = is_cls ? (t >= 1) : (t < T_);

        // gx prefetch BEFORE the barrier (gx has no h dependency)
        float2 gxv[4];
        if (!is_cls && t < T_) {
            const float* gxp = g_gx + ((size_t)t * B_ + ebatch) * G4 + s * 16 + 2 * epr;
#pragma unroll
            for (int g = 0; g < 4; g++)
                gxv[g] = ld_cg_f2(gxp + g * 1024);
        }

        grid_bar_g(bar, (unsigned)(t + 1) * GRP);
        if (!active) continue;
        const int p = t & 1;

        // stage 32x2048B h rows: issue ALL four column-quarter groups now
        const char* hsrc = (const char*)(g_h[p] + (size_t)nb * 32 * I_);
#pragma unroll
        for (int qt = 0; qt < 4; qt++) {
#pragma unroll
            for (int u = 0; u < 4; u++) {
                int i = tid + u * 256;                 // 0..1023
                int row = i >> 5, seg = (i & 31) + qt * 32;
                const char* src = hsrc + row * 2048 + seg * 16;
                uint32_t dst = hsb + (uint32_t)(row * SROW + seg * 16);
                asm volatile("cp.async.cg.shared.global [%0], [%1], 16;"
                             :: "r"(dst), "l"(__cvta_generic_to_global(src)));
            }
            asm volatile("cp.async.commit_group;" ::: "memory");
        }

        float accA[2][4], accB[2][4];
#pragma unroll
        for (int j = 0; j < 2; j++)
#pragma unroll
            for (int q = 0; q < 4; q++) { accA[j][q] = 0.f; accB[j][q] = 0.f; }

        // quarter-pipelined MMA: quarters 0,1 -> accA chains; 2,3 -> accB
#pragma unroll
        for (int qt = 0; qt < 4; qt++) {
            if (qt == 0)      asm volatile("cp.async.wait_group 3;" ::: "memory");
            else if (qt == 1) asm volatile("cp.async.wait_group 2;" ::: "memory");
            else if (qt == 2) asm volatile("cp.async.wait_group 1;" ::: "memory");
            else              asm volatile("cp.async.wait_group 0;" ::: "memory");
            __syncthreads();
#pragma unroll
            for (int qq = 0; qq < 8; qq++) {
                int q = qt * 8 + qq;
                int off = q * 32;
                uint4 a0 = *reinterpret_cast<const uint4*>(pA + off);
                uint4 a1 = *reinterpret_cast<const uint4*>(pA + A8 + off);
                uint4 b0, b1;
                LDS128U(b0, sB0 + q * 64);
                LDS128U(b1, sB1 + q * 64);
                if (qt < 2) {
                    MMA_K32(accA[0], a0, a1, b0);
                    MMA_K32(accA[1], a0, a1, b1);
                } else {
                    MMA_K32(accB[0], a0, a1, b0);
                    MMA_K32(accB[1], a0, a1, b1);
                }
            }
        }

        float acc[2][4];
#pragma unroll
        for (int j = 0; j < 2; j++)
#pragma unroll
            for (int q = 0; q < 4; q++) acc[j][q] = accA[j][q] + accB[j][q];

        if (is_cls) {
            int tq = t - 1;
#pragma unroll
            for (int j = 0; j < 2; j++) {
                int bA = nb * 32 + nw * 16 + j * 8 + 2 * c;
                int row0 = mw * 16 + r, row1 = row0 + 8;
                if (row0 < NC) {
                    float bc = b_cls[row0];
                    out[((size_t)bA       * T_ + tq) * NC + row0] = acc[j][0] + bc;
                    out[((size_t)(bA + 1) * T_ + tq) * NC + row0] = acc[j][1] + bc;
                }
                if (row1 < NC) {
                    float bc = b_cls[row1];
                    out[((size_t)bA       * T_ + tq) * NC + row1] = acc[j][2] + bc;
                    out[((size_t)(bA + 1) * T_ + tq) * NC + row1] = acc[j][3] + bc;
                }
            }
            continue;
        }

#pragma unroll
        for (int j = 0; j < 2; j++) {
            int col = nw * 16 + j * 8 + 2 * c;
            Ds[mw * 16 + r    ][col    ] = acc[j][0];
            Ds[mw * 16 + r    ][col + 1] = acc[j][1];
            Ds[mw * 16 + r + 8][col    ] = acc[j][2];
            Ds[mw * 16 + r + 8][col + 1] = acc[j][3];
        }
        __syncthreads();

        // fused cell update, one k-pair per thread; half2 h store.
        // NOTE: no trailing __syncthreads — cs is per-thread, and Ds/hs reuse
        // is guarded by grid_bar_g's entry+exit syncs next iteration.
        {
            int u0 = 2 * epr, u1 = u0 + 1;
            float gi0 = Ds[u0][eb]      + gxv[0].x;
            float gi1 = Ds[u1][eb]      + gxv[0].y;
            float gf0 = Ds[16 + u0][eb] + gxv[1].x;
            float gf1 = Ds[16 + u1][eb] + gxv[1].y;
            float gg0 = Ds[32 + u0][eb] + gxv[2].x;
            float gg1 = Ds[32 + u1][eb] + gxv[2].y;
            float go0 = Ds[48 + u0][eb] + gxv[3].x;
            float go1 = Ds[48 + u1][eb] + gxv[3].y;
            float cn0 = sigf(gf0) * cs[eb][u0] + sigf(gi0) * tanhf(gg0);
            float cn1 = sigf(gf1) * cs[eb][u1] + sigf(gi1) * tanhf(gg1);
            cs[eb][u0] = cn0;
            cs[eb][u1] = cn1;
            __half2 hv = __floats2half2_rn(sigf(go0) * tanhf(cn0),
                                           sigf(go1) * tanhf(cn1));
            st_cg_u32(&g_h[(t + 1) & 1][(size_t)ebatch * I_ + ehidx],
                      *reinterpret_cast<uint32_t*>(&hv));
        }
    }
    (void)srow;
}

// ---------------------------------------------------------------------------
extern "C" void kernel_launch(void* const* d_in, const int* in_sizes, int n_in,
                              void* d_out, int out_size)
{
    (void)in_sizes; (void)n_in; (void)out_size;
    const float* feat  = (const float*)d_in[0];
    const float* W_pre = (const float*)d_in[1];
    const float* b_pre = (const float*)d_in[2];
    const float* W_ih  = (const float*)d_in[3];
    const float* b_ih  = (const float*)d_in[4];
    const float* W_hh  = (const float*)d_in[5];
    const float* b_hh  = (const float*)d_in[6];
    const float* W_cls = (const float*)d_in[7];
    const float* b_cls = (const float*)d_in[8];
    float* out = (float*)d_out;

    const int SMEM_DYN  = 2 * 16384;
    const int SMEM_PERS = 32 * SROW;            // 67584 B staged h
    static bool attr_done = false;
    if (!attr_done) {
        cudaFuncSetAttribute(lstm_persist,
                             cudaFuncAttributeMaxDynamicSharedMemorySize, SMEM_PERS);
        attr_done = true;
    }

    prep_split<0><<<dim3(F_ / 512, M_), 256>>>(feat,  F_);
    prep_split<1><<<dim3(F_ / 512, I_), 256>>>(W_pre, F_);
    prep_split<2><<<dim3(I_ / 512, G4), 256>>>(W_ih,  I_);

    // Phase 1: x = relu(feat @ W_pre^T + b_pre)      M=32768 N=1024 K=3072
    mma_gemm_s<F_, 0><<<dim3(1024 / 128, M_ / 128), 256, SMEM_DYN>>>(b_pre, nullptr);

    prep_rec<<<dim3(I_ / 512, MP), 256>>>(W_hh, W_cls);
    init_state<<<(B_ * I_ + 255) / 256, 256>>>();

    // Phase 2: gx[t][b] = x @ W_ih^T + b_ih + b_hh   M=32768 N=4096 K=1024
    mma_gemm_s<I_, 1><<<dim3(G4 / 128, M_ / 128), 256, SMEM_DYN>>>(b_ih, b_hh);

    // Phase 3: full recurrence in ONE persistent kernel (513 rounds,
    // two independent 65-block barrier groups, 4-quarter pipelined h staging)
    lstm_persist<<<NBLK, 256, SMEM_PERS>>>(out, b_cls);
}